// round 3
// baseline (speedup 1.0000x reference)
#include <cuda_runtime.h>
#include <math.h>

#define K_ROWS 32768
#define M_COLS 1024
#define NITER  8
#define CR_ROWS 64
#define IT_BLOCKS 512          // k_iter grid: 512 blocks x 64 rows
#define SUBTILES 8             // 8 subtiles of 8 rows per block

#ifndef M_PI
#define M_PI 3.14159265358979323846
#endif

// Scratch (static device globals; no allocation anywhere)
__device__ __align__(16) float g_norm2[M_COLS];
__device__ __align__(16) float g_vraw[M_COLS];
__device__ __align__(16) float g_rinv[M_COLS];
__device__ __align__(16) float g_v[M_COLS];
__device__ __align__(16) float g_x[M_COLS];
__device__ __align__(16) float g_pp[M_COLS];   // pp = x .* rinv (input to A-pass)
__device__ __align__(16) float g_z[M_COLS];    // zraw = A^T A pp (atomic accum)
__device__ int g_cnt = 0;                      // tail-block ticket

// ---------------------------------------------------------------------------
__global__ void k_zero() {
    int j = threadIdx.x;
    g_norm2[j] = 0.0f;
    g_vraw[j]  = 0.0f;
}

// ---------------------------------------------------------------------------
// One streaming pass over weights: per-column sum of squares and per-column
// dot with the input vector. float4 column groups, 64-row chunks, atomics.
__global__ void k_colreduce(const float* __restrict__ A,
                            const float* __restrict__ u) {
    int tx = threadIdx.x;                    // 0..255 -> float4 column group
    int k0 = blockIdx.x * CR_ROWS;
    const float4* A4 = (const float4*)A;     // row stride = 256 float4
    float4 s2 = make_float4(0.f, 0.f, 0.f, 0.f);
    float4 sv = make_float4(0.f, 0.f, 0.f, 0.f);
#pragma unroll 8
    for (int i = 0; i < CR_ROWS; ++i) {
        int k = k0 + i;
        float4 a = A4[k * 256 + tx];
        float uk = __ldg(&u[k]);
        s2.x += a.x * a.x; s2.y += a.y * a.y; s2.z += a.z * a.z; s2.w += a.w * a.w;
        sv.x += uk * a.x;  sv.y += uk * a.y;  sv.z += uk * a.z;  sv.w += uk * a.w;
    }
    int c = tx * 4;
    atomicAdd(&g_norm2[c + 0], s2.x); atomicAdd(&g_norm2[c + 1], s2.y);
    atomicAdd(&g_norm2[c + 2], s2.z); atomicAdd(&g_norm2[c + 3], s2.w);
    atomicAdd(&g_vraw[c + 0], sv.x);  atomicAdd(&g_vraw[c + 1], sv.y);
    atomicAdd(&g_vraw[c + 2], sv.z);  atomicAdd(&g_vraw[c + 3], sv.w);
}

// ---------------------------------------------------------------------------
// rinv = 1/max(||col||,1e-12); v = vraw.*rinv; x0 = v; pp = x0.*rinv; z = 0.
__global__ void k_finalize() {
    int j = threadIdx.x;
    float n  = sqrtf(g_norm2[j]);
    float ri = 1.0f / fmaxf(n, 1e-12f);
    float v  = g_vraw[j] * ri;
    g_rinv[j] = ri;
    g_v[j]    = v;
    g_x[j]    = v;          // x0 = v (good initial guess, R ~ I)
    g_pp[j]   = v * ri;
    g_z[j]    = 0.0f;
}

// ---------------------------------------------------------------------------
// FUSED normal-equation matvec + Richardson update:
//   z = A^T (A * pp)  in one pass over A, then the tail block applies
//   x += alpha*(v - rinv.*z); pp = x.*rinv; z = 0.
//
// Two-phase subtile structure (8 rows per subtile, 8 subtiles per block):
//   Phase 1: warp w streams row (row0+w), dots with p (smem), warp-reduce,
//            q_s[w] <- q_k.           (coalesced DRAM read, fills L1)
//   Phase 2: each thread owns 4 columns; acc4 += q_s[r] * A[row0+r][cols]
//            (re-read of the 32KB subtile hits L1).
// Persistent per-thread state is ONE float4 -> low regs, 4 CTAs/SM.
// `rev` flips subtile traversal per iteration (per-block serpentine) so
// consecutive passes re-read the block's chunk in reverse -> L2 reuse.
__global__ void __launch_bounds__(256, 4) k_iter(const float* __restrict__ A,
                                                 float alpha, int rev) {
    __shared__ float4 p_s[256];
    __shared__ float  q_s[8];
    __shared__ int    is_last;
    int tx = threadIdx.x;
    p_s[tx] = ((const float4*)g_pp)[tx];
    __syncthreads();

    int warp = tx >> 5, lane = tx & 31;
    const float4* A4 = (const float4*)A;
    float4 acc = make_float4(0.f, 0.f, 0.f, 0.f);

    for (int s = 0; s < SUBTILES; ++s) {
        int st = rev ? (SUBTILES - 1 - s) : s;
        int row0 = blockIdx.x * 64 + st * 8;

        // Phase 1: warp w -> q for row (row0 + w)
        {
            const float4* Arow = A4 + (row0 + warp) * 256;
            float d = 0.0f;
#pragma unroll
            for (int i = 0; i < 8; ++i) {
                float4 a = Arow[lane + 32 * i];
                float4 p = p_s[lane + 32 * i];
                d += a.x * p.x + a.y * p.y + a.z * p.z + a.w * p.w;
            }
#pragma unroll
            for (int o = 16; o; o >>= 1) d += __shfl_xor_sync(0xFFFFFFFFu, d, o);
            if (lane == 0) q_s[warp] = d;
        }
        __syncthreads();

        // Phase 2: thread tx accumulates its 4 columns over the 8 rows (L1 hits)
#pragma unroll
        for (int r = 0; r < 8; ++r) {
            float qk = q_s[r];
            float4 a = A4[(row0 + r) * 256 + tx];
            acc.x += qk * a.x; acc.y += qk * a.y;
            acc.z += qk * a.z; acc.w += qk * a.w;
        }
        __syncthreads();
    }

    int c = tx * 4;
    atomicAdd(&g_z[c + 0], acc.x);
    atomicAdd(&g_z[c + 1], acc.y);
    atomicAdd(&g_z[c + 2], acc.z);
    atomicAdd(&g_z[c + 3], acc.w);

    // Tail block performs the Richardson update (threadFenceReduction pattern)
    __threadfence();
    if (tx == 0) {
        int old = atomicAdd(&g_cnt, 1);
        is_last = (old == (int)gridDim.x - 1);
    }
    __syncthreads();
    if (is_last) {
        __threadfence();
#pragma unroll
        for (int k = 0; k < 4; ++k) {
            int j = c + k;
            float x = g_x[j] + alpha * (g_v[j] - g_rinv[j] * g_z[j]);
            g_x[j]  = x;
            g_pp[j] = x * g_rinv[j];
            g_z[j]  = 0.0f;
        }
        if (tx == 0) g_cnt = 0;
    }
}

// ---------------------------------------------------------------------------
// thr = std(x, ddof=1); out = x .* (x > thr).  Single 1024-thread block.
__global__ void k_stats(float* __restrict__ out) {
    __shared__ float red[32];
    int j = threadIdx.x;
    float x = g_x[j];

    float s = x;
#pragma unroll
    for (int o = 16; o; o >>= 1) s += __shfl_xor_sync(0xFFFFFFFFu, s, o);
    if ((j & 31) == 0) red[j >> 5] = s;
    __syncthreads();
    if (j < 32) {
        float t = red[j];
#pragma unroll
        for (int o = 16; o; o >>= 1) t += __shfl_xor_sync(0xFFFFFFFFu, t, o);
        if (j == 0) red[0] = t;
    }
    __syncthreads();
    float mean = red[0] * (1.0f / 1024.0f);
    __syncthreads();   // everyone has read red[0] before phase 2 overwrites

    float d = x - mean;
    float s2 = d * d;
#pragma unroll
    for (int o = 16; o; o >>= 1) s2 += __shfl_xor_sync(0xFFFFFFFFu, s2, o);
    if ((j & 31) == 0) red[j >> 5] = s2;
    __syncthreads();
    if (j < 32) {
        float t = red[j];
#pragma unroll
        for (int o = 16; o; o >>= 1) t += __shfl_xor_sync(0xFFFFFFFFu, t, o);
        if (j == 0) red[0] = t;
    }
    __syncthreads();
    float thr = sqrtf(red[0] * (1.0f / 1023.0f));  // ddof=1, ALPHA=1
    out[j] = (x > thr) ? x : 0.0f;
}

// ---------------------------------------------------------------------------
extern "C" void kernel_launch(void* const* d_in, const int* in_sizes, int n_in,
                              void* d_out, int out_size) {
    const float* inp;
    const float* wts;
    if (in_sizes[0] == K_ROWS) { inp = (const float*)d_in[0]; wts = (const float*)d_in[1]; }
    else                       { inp = (const float*)d_in[1]; wts = (const float*)d_in[0]; }
    float* out = (float*)d_out;

    k_zero<<<1, M_COLS>>>();
    k_colreduce<<<K_ROWS / CR_ROWS, 256>>>(wts, inp);
    k_finalize<<<1, M_COLS>>>();

    // Spectrum bracket for R = W^T W (unit columns, gamma = 1/32 MP law):
    // true eig range ~[0.678, 1.385]; use [0.60, 1.45] with margin.
    const double aa = 0.60, bb = 1.45;
    const double dd = 0.5 * (aa + bb), cc = 0.5 * (bb - aa);
    for (int i = 0; i < NITER; ++i) {
        double lam = dd - cc * cos(M_PI * (2.0 * i + 1.0) / (2.0 * NITER));
        k_iter<<<IT_BLOCKS, 256>>>(wts, (float)(1.0 / lam), i & 1);
    }
    k_stats<<<1, M_COLS>>>(out);
}